// round 5
// baseline (speedup 1.0000x reference)
#include <cuda_runtime.h>

#define NN 1048576
#define EE 8388608
#define GG 32768
#define PS 12   // padded row stride (9 channels + 3 pad) -> 48B, 16B-aligned

// ---------------- device state (no allocation allowed) ----------------
__device__ __align__(16) float  g_hin[(size_t)NN * PS];   // h_in per layer
__device__ __align__(16) float  g_buf[(size_t)NN * PS];   // aggr -> z -> z2
__device__ __align__(16) float  g_vn [(size_t)GG * PS];   // virtual node emb
__device__ __align__(16) float  g_gs [(size_t)GG * PS];   // graph sums / vn_tmp / u2
__device__ double g_statsA[36];
__device__ double g_statsB[36];
__device__ float  g_p1[36];    // BN1 (18ch) scale/shift
__device__ float  g_p2[18];    // BNout (9ch)
__device__ float  g_pv1[36];   // VN BN1 (18ch)
__device__ float  g_pv2[18];   // VN BN2 (9ch)
__device__ double g_outacc[9];

// ---------------- helpers ----------------
__device__ __forceinline__ void red_add4(float* p, float a, float b, float c, float d) {
    asm volatile("red.global.add.v4.f32 [%0], {%1,%2,%3,%4};"
                 :: "l"(__cvta_generic_to_global(p)), "f"(a), "f"(b), "f"(c), "f"(d) : "memory");
}
__device__ __forceinline__ void red_add1(float* p, float a) {
    asm volatile("red.global.add.f32 [%0], %1;"
                 :: "l"(__cvta_generic_to_global(p)), "f"(a) : "memory");
}

// warp-level segmented sum over sorted keys, then 3 vector atomics per segment head
__device__ __forceinline__ void seg_atomic9(int key, float v[9], float* dstBase) {
    int lane = threadIdx.x & 31;
    #pragma unroll
    for (int off = 1; off < 32; off <<= 1) {
        int nk = __shfl_down_sync(0xffffffffu, key, off);
        float t[9];
        #pragma unroll
        for (int k = 0; k < 9; k++) t[k] = __shfl_down_sync(0xffffffffu, v[k], off);
        if (lane + off < 32 && nk == key) {
            #pragma unroll
            for (int k = 0; k < 9; k++) v[k] += t[k];
        }
    }
    int pk = __shfl_up_sync(0xffffffffu, key, 1);
    if (lane == 0 || pk != key) {
        float* p = dstBase + (size_t)key * PS;
        red_add4(p,     v[0], v[1], v[2], v[3]);
        red_add4(p + 4, v[4], v[5], v[6], v[7]);
        red_add1(p + 8, v[8]);
    }
}

// ---------------- kernels ----------------
__global__ void __launch_bounds__(256) k_init() {
    int i = blockIdx.x * 256 + threadIdx.x;
    if (i < GG * PS) { g_vn[i] = 0.f; g_gs[i] = 0.f; }
    if (i < 36) { g_statsA[i] = 0.0; g_statsB[i] = 0.0; }
    if (i < 9)  g_outacc[i] = 0.0;
}

// AtomEncoder: h_in = sum_f atom_emb[f, x[n,f]]; zero msg buffer; graph sums of h_in
__global__ void __launch_bounds__(256) k_atom(const float* __restrict__ atom_emb,
                                              const int* __restrict__ x,
                                              const int* __restrict__ batch) {
    int n = blockIdx.x * 256 + threadIdx.x;   // grid exactly covers NN
    float h[9];
    #pragma unroll
    for (int k = 0; k < 9; k++) h[k] = 0.f;
    #pragma unroll
    for (int f = 0; f < 9; f++) {
        int v = __ldg(x + (size_t)n * 9 + f);
        const float* row = atom_emb + ((size_t)f * 119 + v) * 9;
        #pragma unroll
        for (int k = 0; k < 9; k++) h[k] += __ldg(row + k);
    }
    float4* hp = (float4*)(g_hin + (size_t)n * PS);
    hp[0] = make_float4(h[0], h[1], h[2], h[3]);
    hp[1] = make_float4(h[4], h[5], h[6], h[7]);
    hp[2] = make_float4(h[8], 0.f, 0.f, 0.f);
    float4 zz = make_float4(0.f, 0.f, 0.f, 0.f);
    float4* bp = (float4*)(g_buf + (size_t)n * PS);
    bp[0] = zz; bp[1] = zz; bp[2] = zz;
    int g = __ldg(batch + n);
    seg_atomic9(g, h, g_gs);
}

// GIN message: relu(h_in[src] + bond_emb sum) scatter-added at dst
__global__ void __launch_bounds__(256) k_edge(const float* __restrict__ bond,
                                              const int* __restrict__ src,
                                              const int* __restrict__ dst,
                                              const int* __restrict__ ea) {
    __shared__ float B[162];
    if (threadIdx.x < 162) B[threadIdx.x] = bond[threadIdx.x];
    __syncthreads();
    int e = blockIdx.x * 256 + threadIdx.x;   // grid exactly covers EE
    int s  = __ldg(src + e);
    int d  = __ldg(dst + e);
    int a0 = __ldg(ea + (size_t)3 * e);
    int a1 = __ldg(ea + (size_t)3 * e + 1);
    int a2 = __ldg(ea + (size_t)3 * e + 2);
    const float* b0 = B + a0 * 9;
    const float* b1 = B + 54 + a1 * 9;
    const float* b2 = B + 108 + a2 * 9;
    const float4* hp = (const float4*)(g_hin + (size_t)s * PS);
    float4 h0 = hp[0], h1 = hp[1], h2 = hp[2];
    float hv[9] = {h0.x, h0.y, h0.z, h0.w, h1.x, h1.y, h1.z, h1.w, h2.x};
    float m[9];
    #pragma unroll
    for (int k = 0; k < 9; k++) m[k] = fmaxf(hv[k] + b0[k] + b1[k] + b2[k], 0.f);
    float* p = g_buf + (size_t)d * PS;
    red_add4(p,     m[0], m[1], m[2], m[3]);
    red_add4(p + 4, m[4], m[5], m[6], m[7]);
    red_add1(p + 8, m[8]);
}

// z = (1+eps)*h_in + aggr ; write z ; accumulate stats of z@W1+b1 (18 ch) -> statsA
__global__ void __launch_bounds__(256) k_nodeZ(const float* __restrict__ W1,
                                               const float* __restrict__ b1,
                                               const float* __restrict__ eps_ptr) {
    __shared__ float sW[162], sb[18], racc[36];
    if (threadIdx.x < 162) sW[threadIdx.x] = W1[threadIdx.x];
    if (threadIdx.x < 18)  sb[threadIdx.x] = b1[threadIdx.x];
    if (threadIdx.x < 36)  racc[threadIdx.x] = 0.f;
    __syncthreads();
    float eps1 = 1.f + __ldg(eps_ptr);
    int n = blockIdx.x * 256 + threadIdx.x;
    float4* bp = (float4*)(g_buf + (size_t)n * PS);
    const float4* hp = (const float4*)(g_hin + (size_t)n * PS);
    float4 a = bp[0], b4 = bp[1], c4 = bp[2];
    float4 ha = hp[0], hb = hp[1], hc = hp[2];
    float z[9];
    z[0] = fmaf(eps1, ha.x, a.x);  z[1] = fmaf(eps1, ha.y, a.y);
    z[2] = fmaf(eps1, ha.z, a.z);  z[3] = fmaf(eps1, ha.w, a.w);
    z[4] = fmaf(eps1, hb.x, b4.x); z[5] = fmaf(eps1, hb.y, b4.y);
    z[6] = fmaf(eps1, hb.z, b4.z); z[7] = fmaf(eps1, hb.w, b4.w);
    z[8] = fmaf(eps1, hc.x, c4.x);
    bp[0] = make_float4(z[0], z[1], z[2], z[3]);
    bp[1] = make_float4(z[4], z[5], z[6], z[7]);
    bp[2] = make_float4(z[8], 0.f, 0.f, 0.f);
    int lane = threadIdx.x & 31;
    #pragma unroll
    for (int c = 0; c < 18; c++) {
        float z1 = sb[c];
        #pragma unroll
        for (int i = 0; i < 9; i++) z1 = fmaf(z[i], sW[i * 18 + c], z1);
        float s = z1, q = z1 * z1;
        #pragma unroll
        for (int off = 16; off > 0; off >>= 1) {
            s += __shfl_down_sync(0xffffffffu, s, off);
            q += __shfl_down_sync(0xffffffffu, q, off);
        }
        if (lane == 0) { atomicAdd(&racc[c], s); atomicAdd(&racc[18 + c], q); }
    }
    __syncthreads();
    if (threadIdx.x < 36) atomicAdd(&g_statsA[threadIdx.x], (double)racc[threadIdx.x]);
}

// finalize BN params (scale = g*invstd, shift = b - mean*scale) and reset stats
__global__ void k_finalize(int statsSel, int paramSel, int C, double invN,
                           const float* __restrict__ gamma, const float* __restrict__ beta) {
    int c = threadIdx.x;
    if (c >= C) return;
    double* st = statsSel ? g_statsB : g_statsA;
    float* P = (paramSel == 0) ? g_p1 : (paramSel == 1) ? g_p2 : (paramSel == 2) ? g_pv1 : g_pv2;
    double mean = st[c] * invN;
    double var  = st[C + c] * invN - mean * mean;
    float inv = rsqrtf((float)var + 1e-5f);
    float sc = __ldg(gamma + c) * inv;
    P[c] = sc;
    P[C + c] = __ldg(beta + c) - (float)mean * sc;
    st[c] = 0.0; st[C + c] = 0.0;
}

// y = relu(BN1(z@W1+b1)); z2 = y@W2+b2 ; write z2 ; stats of z2 (9 ch) -> statsB
__global__ void __launch_bounds__(256) k_nodeY(const float* __restrict__ W1,
                                               const float* __restrict__ b1,
                                               const float* __restrict__ W2,
                                               const float* __restrict__ b2) {
    __shared__ float sW1[162], sW2[162], sb1[18], sb2[9], sP[36], racc[36];
    if (threadIdx.x < 162) { sW1[threadIdx.x] = W1[threadIdx.x]; sW2[threadIdx.x] = W2[threadIdx.x]; }
    if (threadIdx.x < 18) sb1[threadIdx.x] = b1[threadIdx.x];
    if (threadIdx.x < 9)  sb2[threadIdx.x] = b2[threadIdx.x];
    if (threadIdx.x < 36) { sP[threadIdx.x] = g_p1[threadIdx.x]; racc[threadIdx.x] = 0.f; }
    __syncthreads();
    int n = blockIdx.x * 256 + threadIdx.x;
    float4* bp = (float4*)(g_buf + (size_t)n * PS);
    float4 a = bp[0], b4 = bp[1], c4 = bp[2];
    float z[9] = {a.x, a.y, a.z, a.w, b4.x, b4.y, b4.z, b4.w, c4.x};
    float y[18];
    #pragma unroll
    for (int c = 0; c < 18; c++) {
        float z1 = sb1[c];
        #pragma unroll
        for (int i = 0; i < 9; i++) z1 = fmaf(z[i], sW1[i * 18 + c], z1);
        y[c] = fmaxf(fmaf(z1, sP[c], sP[18 + c]), 0.f);
    }
    float z2[9];
    #pragma unroll
    for (int c = 0; c < 9; c++) {
        float acc = sb2[c];
        #pragma unroll
        for (int j = 0; j < 18; j++) acc = fmaf(y[j], sW2[j * 9 + c], acc);
        z2[c] = acc;
    }
    bp[0] = make_float4(z2[0], z2[1], z2[2], z2[3]);
    bp[1] = make_float4(z2[4], z2[5], z2[6], z2[7]);
    bp[2] = make_float4(z2[8], 0.f, 0.f, 0.f);
    int lane = threadIdx.x & 31;
    #pragma unroll
    for (int c = 0; c < 9; c++) {
        float s = z2[c], q = z2[c] * z2[c];
        #pragma unroll
        for (int off = 16; off > 0; off >>= 1) {
            s += __shfl_down_sync(0xffffffffu, s, off);
            q += __shfl_down_sync(0xffffffffu, q, off);
        }
        if (lane == 0) { atomicAdd(&racc[c], s); atomicAdd(&racc[9 + c], q); }
    }
    __syncthreads();
    if (threadIdx.x < 18) atomicAdd(&g_statsB[threadIdx.x], (double)racc[threadIdx.x]);
}

// VN step A: vn_tmp = graphsum + vn (stored back into g_gs); stats of vn_tmp@vnW1+vnb1 -> statsA
__global__ void __launch_bounds__(256) k_vnA(const float* __restrict__ W1,
                                             const float* __restrict__ b1) {
    __shared__ float sW[162], sb[18], racc[36];
    if (threadIdx.x < 162) sW[threadIdx.x] = W1[threadIdx.x];
    if (threadIdx.x < 18)  sb[threadIdx.x] = b1[threadIdx.x];
    if (threadIdx.x < 36)  racc[threadIdx.x] = 0.f;
    __syncthreads();
    int g = blockIdx.x * 256 + threadIdx.x;   // grid exactly covers GG
    float4* gp = (float4*)(g_gs + (size_t)g * PS);
    const float4* vp = (const float4*)(g_vn + (size_t)g * PS);
    float4 a = gp[0], b4 = gp[1], c4 = gp[2];
    float4 va = vp[0], vb = vp[1], vc = vp[2];
    float vt[9] = {a.x + va.x, a.y + va.y, a.z + va.z, a.w + va.w,
                   b4.x + vb.x, b4.y + vb.y, b4.z + vb.z, b4.w + vb.w, c4.x + vc.x};
    gp[0] = make_float4(vt[0], vt[1], vt[2], vt[3]);
    gp[1] = make_float4(vt[4], vt[5], vt[6], vt[7]);
    gp[2] = make_float4(vt[8], 0.f, 0.f, 0.f);
    int lane = threadIdx.x & 31;
    #pragma unroll
    for (int c = 0; c < 18; c++) {
        float u = sb[c];
        #pragma unroll
        for (int i = 0; i < 9; i++) u = fmaf(vt[i], sW[i * 18 + c], u);
        float s = u, q = u * u;
        #pragma unroll
        for (int off = 16; off > 0; off >>= 1) {
            s += __shfl_down_sync(0xffffffffu, s, off);
            q += __shfl_down_sync(0xffffffffu, q, off);
        }
        if (lane == 0) { atomicAdd(&racc[c], s); atomicAdd(&racc[18 + c], q); }
    }
    __syncthreads();
    if (threadIdx.x < 36) atomicAdd(&g_statsA[threadIdx.x], (double)racc[threadIdx.x]);
}

// VN step B: t = relu(BN1(u1)); u2 = t@vnW2+vnb2 (stored into g_gs); stats of u2 -> statsB
__global__ void __launch_bounds__(256) k_vnB(const float* __restrict__ W1,
                                             const float* __restrict__ b1,
                                             const float* __restrict__ W2,
                                             const float* __restrict__ b2) {
    __shared__ float sW1[162], sW2[162], sb1[18], sb2[9], sP[36], racc[36];
    if (threadIdx.x < 162) { sW1[threadIdx.x] = W1[threadIdx.x]; sW2[threadIdx.x] = W2[threadIdx.x]; }
    if (threadIdx.x < 18) sb1[threadIdx.x] = b1[threadIdx.x];
    if (threadIdx.x < 9)  sb2[threadIdx.x] = b2[threadIdx.x];
    if (threadIdx.x < 36) { sP[threadIdx.x] = g_pv1[threadIdx.x]; racc[threadIdx.x] = 0.f; }
    __syncthreads();
    int g = blockIdx.x * 256 + threadIdx.x;
    float4* gp = (float4*)(g_gs + (size_t)g * PS);
    float4 a = gp[0], b4 = gp[1], c4 = gp[2];
    float vt[9] = {a.x, a.y, a.z, a.w, b4.x, b4.y, b4.z, b4.w, c4.x};
    float t1[18];
    #pragma unroll
    for (int c = 0; c < 18; c++) {
        float u = sb1[c];
        #pragma unroll
        for (int i = 0; i < 9; i++) u = fmaf(vt[i], sW1[i * 18 + c], u);
        t1[c] = fmaxf(fmaf(u, sP[c], sP[18 + c]), 0.f);
    }
    float u2[9];
    #pragma unroll
    for (int c = 0; c < 9; c++) {
        float acc = sb2[c];
        #pragma unroll
        for (int j = 0; j < 18; j++) acc = fmaf(t1[j], sW2[j * 9 + c], acc);
        u2[c] = acc;
    }
    gp[0] = make_float4(u2[0], u2[1], u2[2], u2[3]);
    gp[1] = make_float4(u2[4], u2[5], u2[6], u2[7]);
    gp[2] = make_float4(u2[8], 0.f, 0.f, 0.f);
    int lane = threadIdx.x & 31;
    #pragma unroll
    for (int c = 0; c < 9; c++) {
        float s = u2[c], q = u2[c] * u2[c];
        #pragma unroll
        for (int off = 16; off > 0; off >>= 1) {
            s += __shfl_down_sync(0xffffffffu, s, off);
            q += __shfl_down_sync(0xffffffffu, q, off);
        }
        if (lane == 0) { atomicAdd(&racc[c], s); atomicAdd(&racc[9 + c], q); }
    }
    __syncthreads();
    if (threadIdx.x < 18) atomicAdd(&g_statsB[threadIdx.x], (double)racc[threadIdx.x]);
}

// VN step C: vn += relu(BN2(u2)); zero graph-sum buffer for next layer
__global__ void __launch_bounds__(256) k_vnC() {
    int g = blockIdx.x * 256 + threadIdx.x;
    float4* gp = (float4*)(g_gs + (size_t)g * PS);
    float4* vp = (float4*)(g_vn + (size_t)g * PS);
    float4 a = gp[0], b4 = gp[1], c4 = gp[2];
    float u2[9] = {a.x, a.y, a.z, a.w, b4.x, b4.y, b4.z, b4.w, c4.x};
    float4 va = vp[0], vb = vp[1], vc = vp[2];
    float vo[9] = {va.x, va.y, va.z, va.w, vb.x, vb.y, vb.z, vb.w, vc.x};
    #pragma unroll
    for (int k = 0; k < 9; k++) {
        float sc = __ldg(&g_pv2[k]), sh = __ldg(&g_pv2[9 + k]);
        vo[k] += fmaxf(fmaf(u2[k], sc, sh), 0.f);
    }
    vp[0] = make_float4(vo[0], vo[1], vo[2], vo[3]);
    vp[1] = make_float4(vo[4], vo[5], vo[6], vo[7]);
    vp[2] = make_float4(vo[8], 0.f, 0.f, 0.f);
    float4 zz = make_float4(0.f, 0.f, 0.f, 0.f);
    gp[0] = zz; gp[1] = zz; gp[2] = zz;
}

// layer finish (l<2): h_new = relu(BNout(z2)) + h_in; h_in' = h_new + vn'[batch];
// zero msg buffer; optionally accumulate next-layer graph sums
__global__ void __launch_bounds__(256) k_final_mid(const int* __restrict__ batch, int accumGS) {
    __shared__ float sP[18];
    if (threadIdx.x < 18) sP[threadIdx.x] = g_p2[threadIdx.x];
    __syncthreads();
    int n = blockIdx.x * 256 + threadIdx.x;
    float4* bp = (float4*)(g_buf + (size_t)n * PS);
    float4* hp = (float4*)(g_hin + (size_t)n * PS);
    float4 a = bp[0], b4 = bp[1], c4 = bp[2];
    float z2[9] = {a.x, a.y, a.z, a.w, b4.x, b4.y, b4.z, b4.w, c4.x};
    float4 ha = hp[0], hb = hp[1], hc = hp[2];
    float hi[9] = {ha.x, ha.y, ha.z, ha.w, hb.x, hb.y, hb.z, hb.w, hc.x};
    int g = __ldg(batch + n);
    const float4* vp = (const float4*)(g_vn + (size_t)g * PS);
    float4 va = vp[0], vb = vp[1], vc = vp[2];
    float vn9[9] = {va.x, va.y, va.z, va.w, vb.x, vb.y, vb.z, vb.w, vc.x};
    float hx[9];
    #pragma unroll
    for (int k = 0; k < 9; k++) {
        float zn = fmaxf(fmaf(z2[k], sP[k], sP[9 + k]), 0.f);
        hx[k] = zn + hi[k] + vn9[k];
    }
    hp[0] = make_float4(hx[0], hx[1], hx[2], hx[3]);
    hp[1] = make_float4(hx[4], hx[5], hx[6], hx[7]);
    hp[2] = make_float4(hx[8], 0.f, 0.f, 0.f);
    float4 zz = make_float4(0.f, 0.f, 0.f, 0.f);
    bp[0] = zz; bp[1] = zz; bp[2] = zz;
    if (accumGS) seg_atomic9(g, hx, g_gs);
}

// last layer finish: h = BNout(z2) + h_in (no relu); global sum -> g_outacc (double)
__global__ void __launch_bounds__(256) k_final_last() {
    __shared__ float sP[18], racc[9];
    if (threadIdx.x < 18) sP[threadIdx.x] = g_p2[threadIdx.x];
    if (threadIdx.x < 9)  racc[threadIdx.x] = 0.f;
    __syncthreads();
    int n = blockIdx.x * 256 + threadIdx.x;
    const float4* bp = (const float4*)(g_buf + (size_t)n * PS);
    const float4* hp = (const float4*)(g_hin + (size_t)n * PS);
    float4 a = bp[0], b4 = bp[1], c4 = bp[2];
    float z2[9] = {a.x, a.y, a.z, a.w, b4.x, b4.y, b4.z, b4.w, c4.x};
    float4 ha = hp[0], hb = hp[1], hc = hp[2];
    float hi[9] = {ha.x, ha.y, ha.z, ha.w, hb.x, hb.y, hb.z, hb.w, hc.x};
    int lane = threadIdx.x & 31;
    #pragma unroll
    for (int k = 0; k < 9; k++) {
        float h = fmaf(z2[k], sP[k], sP[9 + k]) + hi[k];
        #pragma unroll
        for (int off = 16; off > 0; off >>= 1)
            h += __shfl_down_sync(0xffffffffu, h, off);
        if (lane == 0) atomicAdd(&racc[k], h);
    }
    __syncthreads();
    if (threadIdx.x < 9) atomicAdd(&g_outacc[threadIdx.x], (double)racc[threadIdx.x]);
}

__global__ void k_out(float* __restrict__ out) {
    if (threadIdx.x < 9) out[threadIdx.x] = (float)g_outacc[threadIdx.x];
}

// ---------------- host ----------------
extern "C" void kernel_launch(void* const* d_in, const int* in_sizes, int n_in,
                              void* d_out, int out_size) {
    const float* atom_emb = (const float*)d_in[0];
    const float* bond_emb = (const float*)d_in[1];
    const float* eps_gin  = (const float*)d_in[2];
    const float* W1       = (const float*)d_in[3];
    const float* b1       = (const float*)d_in[4];
    const float* bn1_g    = (const float*)d_in[5];
    const float* bn1_b    = (const float*)d_in[6];
    const float* W2       = (const float*)d_in[7];
    const float* b2       = (const float*)d_in[8];
    const float* bno_g    = (const float*)d_in[9];
    const float* bno_b    = (const float*)d_in[10];
    const float* vnW1     = (const float*)d_in[11];
    const float* vnb1     = (const float*)d_in[12];
    const float* vnbn1_g  = (const float*)d_in[13];
    const float* vnbn1_b  = (const float*)d_in[14];
    const float* vnW2     = (const float*)d_in[15];
    const float* vnb2     = (const float*)d_in[16];
    const float* vnbn2_g  = (const float*)d_in[17];
    const float* vnbn2_b  = (const float*)d_in[18];
    const int*   x        = (const int*)d_in[19];
    const int*   eidx     = (const int*)d_in[20];
    const int*   eattr    = (const int*)d_in[21];
    const int*   batch    = (const int*)d_in[22];
    (void)in_sizes; (void)n_in; (void)out_size;

    const int NB_N = NN / 256;        // 4096
    const int NB_E = EE / 256;        // 32768
    const int NB_G = GG / 256;        // 128
    const double invN = 1.0 / (double)NN;
    const double invG = 1.0 / (double)GG;

    k_init<<<(GG * PS + 255) / 256, 256>>>();
    k_atom<<<NB_N, 256>>>(atom_emb, x, batch);

    for (int l = 0; l < 3; l++) {
        k_edge<<<NB_E, 256>>>(bond_emb + l * 162, eidx, eidx + EE, eattr);
        k_nodeZ<<<NB_N, 256>>>(W1 + l * 162, b1 + l * 18, eps_gin + l);
        k_finalize<<<1, 32>>>(0, 0, 18, invN, bn1_g + l * 18, bn1_b + l * 18);
        k_nodeY<<<NB_N, 256>>>(W1 + l * 162, b1 + l * 18, W2 + l * 162, b2 + l * 9);
        k_finalize<<<1, 32>>>(1, 1, 9, invN, bno_g + l * 9, bno_b + l * 9);
        if (l < 2) {
            k_vnA<<<NB_G, 256>>>(vnW1 + l * 162, vnb1 + l * 18);
            k_finalize<<<1, 32>>>(0, 2, 18, invG, vnbn1_g + l * 18, vnbn1_b + l * 18);
            k_vnB<<<NB_G, 256>>>(vnW1 + l * 162, vnb1 + l * 18, vnW2 + l * 162, vnb2 + l * 9);
            k_finalize<<<1, 32>>>(1, 3, 9, invG, vnbn2_g + l * 9, vnbn2_b + l * 9);
            k_vnC<<<NB_G, 256>>>();
            k_final_mid<<<NB_N, 256>>>(batch, (l == 0) ? 1 : 0);
        } else {
            k_final_last<<<NB_N, 256>>>();
        }
    }
    k_out<<<1, 32>>>((float*)d_out);
}